// round 1
// baseline (speedup 1.0000x reference)
#include <cuda_runtime.h>
#include <math.h>
#include <stdint.h>

// Problem constants (fixed by the reference)
#define Bsz   2
#define Tseq  1024
#define NQH   32
#define NKV   8
#define Dh    128
#define BM    64      // query rows per CTA
#define BN    64      // key rows per tile
#define DPAD  132     // padded row length for Q/K/V tiles (floats)
#define SPAD  65      // padded row length for S/P tile (floats)
#define NTHREADS 256
#define MASKV (-3.0e38f)

// Shared memory layout (floats):
//  sQ  [BM][DPAD]   Q tile
//  sKV [BN][DPAD]   K tile, then overwritten by V tile
//  sS  [BM][SPAD]   logits -> probabilities
//  sM, sL, sScale [BM]
//  sSegQ, sSegK [BM] ints
#define SMEM_BYTES ((BM*DPAD + BN*DPAD + BM*SPAD + 3*BM) * 4 + 2*BM*4)

__global__ __launch_bounds__(NTHREADS, 2)
void attn_fa_kernel(const float* __restrict__ Q,
                    const float* __restrict__ K,
                    const float* __restrict__ V,
                    const int*   __restrict__ seg,
                    float*       __restrict__ O)
{
    extern __shared__ char smem_raw[];
    float* sQ     = (float*)smem_raw;
    float* sKV    = sQ  + BM * DPAD;
    float* sS     = sKV + BN * DPAD;
    float* sM     = sS  + BM * SPAD;
    float* sL     = sM  + BM;
    float* sScale = sL  + BM;
    int*   sSegQ  = (int*)(sScale + BM);
    int*   sSegK  = sSegQ + BM;

    const int tid   = threadIdx.x;
    const int qtile = blockIdx.x;      // 0..15
    const int h     = blockIdx.y;      // 0..31
    const int b     = blockIdx.z;      // 0..1
    const int kh    = h >> 2;          // GQA group of 4
    const int q0    = qtile * BM;

    const int tx = tid & 15;           // column group
    const int ty = tid >> 4;           // row group

    // ---- load Q tile (coalesced float4) ----
    {
        const float4* Qg = (const float4*)Q;
        #pragma unroll
        for (int i = tid; i < BM * Dh / 4; i += NTHREADS) {
            int r  = i >> 5;           // 32 float4 per row
            int c4 = i & 31;
            float4 v = Qg[((size_t)((b * Tseq + q0 + r) * NQH + h) * Dh >> 2) + c4];
            *(float4*)&sQ[r * DPAD + (c4 << 2)] = v;
        }
    }
    if (tid < BM) {
        sSegQ[tid] = seg[b * Tseq + q0 + tid];
        sM[tid] = MASKV;
        sL[tid] = 0.0f;
    }
    __syncthreads();

    const int segqmin = sSegQ[0];        // seg ids sorted along T
    const int segqmax = sSegQ[BM - 1];

    float acc[4][8];
    #pragma unroll
    for (int i = 0; i < 4; i++)
        #pragma unroll
        for (int j = 0; j < 8; j++) acc[i][j] = 0.0f;

    for (int kt = 0; kt <= qtile; ++kt) {
        const int k0 = kt * BN;
        // tile-level segment skip (seg sorted -> range check)
        const int skmin = seg[b * Tseq + k0];
        const int skmax = seg[b * Tseq + k0 + BN - 1];
        if (skmax < segqmin || skmin > segqmax) continue;

        // ---- load K tile ----
        {
            const float4* Kg = (const float4*)K;
            #pragma unroll
            for (int i = tid; i < BN * Dh / 4; i += NTHREADS) {
                int r  = i >> 5;
                int c4 = i & 31;
                float4 v = Kg[((size_t)((b * Tseq + k0 + r) * NKV + kh) * Dh >> 2) + c4];
                *(float4*)&sKV[r * DPAD + (c4 << 2)] = v;
            }
        }
        if (tid < BN) sSegK[tid] = seg[b * Tseq + k0 + tid];
        __syncthreads();

        // ---- S = Q @ K^T : per-thread 4x4, rows ty+16i, cols tx+16j ----
        float sreg[4][4];
        #pragma unroll
        for (int i = 0; i < 4; i++)
            #pragma unroll
            for (int j = 0; j < 4; j++) sreg[i][j] = 0.0f;

        for (int k = 0; k < Dh; k += 4) {
            float4 qv[4];
            #pragma unroll
            for (int i = 0; i < 4; i++)
                qv[i] = *(const float4*)&sQ[(ty + 16 * i) * DPAD + k];
            #pragma unroll
            for (int kk = 0; kk < 4; kk++) {
                float kvv[4];
                #pragma unroll
                for (int j = 0; j < 4; j++)
                    kvv[j] = sKV[(tx + 16 * j) * DPAD + k + kk];
                #pragma unroll
                for (int i = 0; i < 4; i++) {
                    float qk = ((const float*)&qv[i])[kk];
                    #pragma unroll
                    for (int j = 0; j < 4; j++)
                        sreg[i][j] += qk * kvv[j];
                }
            }
        }

        // write S to smem
        #pragma unroll
        for (int i = 0; i < 4; i++)
            #pragma unroll
            for (int j = 0; j < 4; j++)
                sS[(ty + 16 * i) * SPAD + tx + 16 * j] = sreg[i][j];
        __syncthreads();

        // ---- load V tile (overwrites sKV; safe: K reads complete) ----
        {
            const float4* Vg = (const float4*)V;
            #pragma unroll
            for (int i = tid; i < BN * Dh / 4; i += NTHREADS) {
                int r  = i >> 5;
                int c4 = i & 31;
                float4 v = Vg[((size_t)((b * Tseq + k0 + r) * NKV + kh) * Dh >> 2) + c4];
                *(float4*)&sKV[r * DPAD + (c4 << 2)] = v;
            }
        }

        // ---- online softmax: one thread per query row ----
        if (tid < BM) {
            const int r  = tid;
            const int sq = sSegQ[r];
            const int qg = q0 + r;
            const float mold = sM[r];
            float mx = mold;
            for (int j = 0; j < BN; ++j) {
                bool ok = (sSegK[j] == sq) && ((k0 + j) <= qg);
                float v = ok ? sS[r * SPAD + j] : MASKV;
                mx = fmaxf(mx, v);
            }
            // mold==mx==MASKV -> scale=1 (garbage epoch zeroed once a real key arrives)
            float scale = __expf(mold - mx);
            float l = sL[r] * scale;
            for (int j = 0; j < BN; ++j) {
                bool ok = (sSegK[j] == sq) && ((k0 + j) <= qg);
                float e = ok ? __expf(sS[r * SPAD + j] - mx) : 0.0f;
                sS[r * SPAD + j] = e;
                l += e;
            }
            sM[r] = mx;
            sL[r] = l;
            sScale[r] = scale;
        }
        __syncthreads();

        // ---- rescale O accumulators, then O += P @ V (4x8 per thread) ----
        float scl[4];
        #pragma unroll
        for (int i = 0; i < 4; i++) scl[i] = sScale[ty + 16 * i];
        #pragma unroll
        for (int i = 0; i < 4; i++)
            #pragma unroll
            for (int j = 0; j < 8; j++) acc[i][j] *= scl[i];

        for (int k = 0; k < BN; ++k) {
            float p[4];
            #pragma unroll
            for (int i = 0; i < 4; i++)
                p[i] = sS[(ty + 16 * i) * SPAD + k];
            float vv[8];
            #pragma unroll
            for (int j = 0; j < 8; j++)
                vv[j] = sKV[k * DPAD + tx + 16 * j];
            #pragma unroll
            for (int i = 0; i < 4; i++)
                #pragma unroll
                for (int j = 0; j < 8; j++)
                    acc[i][j] += p[i] * vv[j];
        }
        __syncthreads();   // protect sKV/sS before next tile's loads
    }

    // ---- epilogue: normalize and store ----
    #pragma unroll
    for (int i = 0; i < 4; i++) {
        const int r  = ty + 16 * i;
        const float inv = 1.0f / sL[r];
        const int tg = q0 + r;
        #pragma unroll
        for (int j = 0; j < 8; j++) {
            const int c = tx + 16 * j;
            O[(size_t)((b * Tseq + tg) * NQH + h) * Dh + c] = acc[i][j] * inv;
        }
    }
}

extern "C" void kernel_launch(void* const* d_in, const int* in_sizes, int n_in,
                              void* d_out, int out_size)
{
    const float* Q   = (const float*)d_in[0];
    const float* K   = (const float*)d_in[1];
    const float* V   = (const float*)d_in[2];
    const int*   seg = (const int*)d_in[3];
    float*       O   = (float*)d_out;

    // idempotent; legal during graph capture (not a stream op)
    cudaFuncSetAttribute(attn_fa_kernel,
                         cudaFuncAttributeMaxDynamicSharedMemorySize, SMEM_BYTES);

    dim3 grid(Tseq / BM, NQH, Bsz);
    attn_fa_kernel<<<grid, NTHREADS, SMEM_BYTES>>>(Q, K, V, seg, O);
}

// round 3
// speedup vs baseline: 2.9915x; 2.9915x over previous
#include <cuda_runtime.h>
#include <cuda_fp16.h>
#include <cstdint>

// ---------------- problem constants ----------------
#define Bsz   2
#define Tseq  1024
#define NQH   32
#define NKV   8
#define Dh    128
#define BM    128        // query rows per CTA
#define BN    64         // key rows per tile
#define NTHREADS 256
#define MASKV (-3.0e38f)

// ---------------- smem layout (bytes) ----------------
// fp16 tiles, 256B rows (128 halves), XOR-swizzled 16B chunks
#define OFF_QHI 0
#define OFF_QLO 32768
#define OFF_KHI 65536
#define OFF_KLO 81920
#define OFF_VHI 98304
#define OFF_VLO 114688
#define OFF_SEGK 131072
#define SMEM_TOTAL (131072 + 256 + 128)

__device__ __forceinline__ uint32_t smem_u32(const void* p) {
    uint32_t a;
    asm("{ .reg .u64 t; cvta.to.shared.u64 t, %1; cvt.u32.u64 %0, t; }"
        : "=r"(a) : "l"(p));
    return a;
}

// swizzled byte offset of 16B chunk (row, c) in a 256B-row tile
__device__ __forceinline__ uint32_t toff(int row, int c) {
    return ((uint32_t)row << 8) + (((uint32_t)(c ^ (row & 7))) << 4);
}

__device__ __forceinline__ void ldsm4(uint32_t* r, uint32_t a) {
    asm volatile("ldmatrix.sync.aligned.m8n8.x4.shared.b16 {%0,%1,%2,%3}, [%4];"
                 : "=r"(r[0]), "=r"(r[1]), "=r"(r[2]), "=r"(r[3]) : "r"(a));
}
__device__ __forceinline__ void ldsm2(uint32_t* r, uint32_t a) {
    asm volatile("ldmatrix.sync.aligned.m8n8.x2.shared.b16 {%0,%1}, [%2];"
                 : "=r"(r[0]), "=r"(r[1]) : "r"(a));
}
__device__ __forceinline__ void ldsm2t(uint32_t* r, uint32_t a) {
    asm volatile("ldmatrix.sync.aligned.m8n8.x2.trans.shared.b16 {%0,%1}, [%2];"
                 : "=r"(r[0]), "=r"(r[1]) : "r"(a));
}
__device__ __forceinline__ void mma16816(float* d, const uint32_t* a, const uint32_t* b) {
    asm volatile("mma.sync.aligned.m16n8k16.row.col.f32.f16.f16.f32 "
                 "{%0,%1,%2,%3}, {%4,%5,%6,%7}, {%8,%9}, {%0,%1,%2,%3};"
                 : "+f"(d[0]), "+f"(d[1]), "+f"(d[2]), "+f"(d[3])
                 : "r"(a[0]), "r"(a[1]), "r"(a[2]), "r"(a[3]),
                   "r"(b[0]), "r"(b[1]));
}

// split (x,y) into fp16 hi pair + fp16 residual-lo pair
__device__ __forceinline__ void split2(float x, float y, uint32_t& h, uint32_t& l) {
    __half hx = __float2half_rn(x), hy = __float2half_rn(y);
    __half lx = __float2half_rn(x - __half2float(hx));
    __half ly = __float2half_rn(y - __half2float(hy));
    __half2 hh = __halves2half2(hx, hy);
    __half2 ll = __halves2half2(lx, ly);
    h = *(uint32_t*)&hh;
    l = *(uint32_t*)&ll;
}

// convert 8 floats -> hi/lo fp16 chunks, store as two st.shared.v4
__device__ __forceinline__ void cvt_sts8(uint32_t ahi, uint32_t alo, const float* v) {
    uint32_t h[4], l[4];
    #pragma unroll
    for (int i = 0; i < 4; i++)
        split2(v[2*i], v[2*i+1], h[i], l[i]);
    asm volatile("st.shared.v4.b32 [%0], {%1,%2,%3,%4};"
                 :: "r"(ahi), "r"(h[0]), "r"(h[1]), "r"(h[2]), "r"(h[3]) : "memory");
    asm volatile("st.shared.v4.b32 [%0], {%1,%2,%3,%4};"
                 :: "r"(alo), "r"(l[0]), "r"(l[1]), "r"(l[2]), "r"(l[3]) : "memory");
}

__global__ __launch_bounds__(NTHREADS, 1)
void attn_hmma_kernel(const float* __restrict__ Q,
                      const float* __restrict__ K,
                      const float* __restrict__ V,
                      const int*   __restrict__ seg,
                      float*       __restrict__ Out)
{
    extern __shared__ char smem[];
    const uint32_t sb = smem_u32(smem);
    const int tid  = threadIdx.x;
    const int wid  = tid >> 5;
    const int lane = tid & 31;
    const int quad = lane >> 2;
    const int qr   = lane & 3;

    const int qtile = blockIdx.x;
    const int h     = blockIdx.y;
    const int b     = blockIdx.z;
    const int kh    = h >> 2;
    const int q0    = qtile * BM;

    int* sSegK = (int*)(smem + OFF_SEGK);

    // ---- prologue: Q -> fp16 hi/lo smem (swizzled) ----
    #pragma unroll
    for (int it = 0; it < 8; it++) {
        int idx = tid + it * NTHREADS;
        int r = idx >> 4, c = idx & 15;
        const float* g = Q + ((size_t)((b * Tseq + q0 + r) * NQH + h)) * Dh + c * 8;
        float4 v0 = *(const float4*)g;
        float4 v1 = *(const float4*)(g + 4);
        float arr[8] = { v0.x, v0.y, v0.z, v0.w, v1.x, v1.y, v1.z, v1.w };
        uint32_t o = toff(r, c);
        cvt_sts8(sb + OFF_QHI + o, sb + OFF_QLO + o, arr);
    }

    // per-row segment ids for this thread's two fragment rows
    const int rowl0 = 16 * wid + quad;          // local row of frag row 0
    const int row0  = q0 + rowl0;               // global q index
    const int sq0 = seg[b * Tseq + row0];
    const int sq1 = seg[b * Tseq + row0 + 8];
    const int sqmin = seg[b * Tseq + q0];
    const int sqmax = seg[b * Tseq + q0 + BM - 1];

    // A-operand ldmatrix addressing (Q tiles)
    const int rA    = 16 * wid + (lane & 15);
    const uint32_t aoff_base = (uint32_t)rA << 8;
    const int aswz   = rA & 7;
    const int achunk = lane >> 4;

    // persistent state
    float m0 = MASKV, m1 = MASKV, l0 = 0.0f, l1 = 0.0f;
    float Oa[16][4];
    #pragma unroll
    for (int i = 0; i < 16; i++)
        #pragma unroll
        for (int j = 0; j < 4; j++) Oa[i][j] = 0.0f;

    const float NEG = -__int_as_float(0x7f800000);  // -inf
    const int ktmax = 2 * qtile + 1;

    for (int kt = 0; kt <= ktmax; kt++) {
        const int k0 = kt * BN;
        const int skmin = seg[b * Tseq + k0];
        const int skmax = seg[b * Tseq + k0 + BN - 1];
        if (skmax < sqmin || skmin > sqmax) continue;  // uniform skip

        __syncthreads();   // prior smem reads complete (and Q stores, first iter)

        // ---- K and V tiles -> fp16 hi/lo smem ----
        #pragma unroll
        for (int it = 0; it < 4; it++) {
            int idx = tid + it * NTHREADS;
            int r = idx >> 4, c = idx & 15;
            uint32_t o = toff(r, c);
            {
                const float* g = K + ((size_t)((b * Tseq + k0 + r) * NKV + kh)) * Dh + c * 8;
                float4 v0 = *(const float4*)g;
                float4 v1 = *(const float4*)(g + 4);
                float arr[8] = { v0.x, v0.y, v0.z, v0.w, v1.x, v1.y, v1.z, v1.w };
                cvt_sts8(sb + OFF_KHI + o, sb + OFF_KLO + o, arr);
            }
            {
                const float* g = V + ((size_t)((b * Tseq + k0 + r) * NKV + kh)) * Dh + c * 8;
                float4 v0 = *(const float4*)g;
                float4 v1 = *(const float4*)(g + 4);
                float arr[8] = { v0.x, v0.y, v0.z, v0.w, v1.x, v1.y, v1.z, v1.w };
                cvt_sts8(sb + OFF_VHI + o, sb + OFF_VLO + o, arr);
            }
        }
        if (tid < BN) sSegK[tid] = seg[b * Tseq + k0 + tid];
        __syncthreads();

        // ---- QK: S(16x64 per warp) = 3-pass fp16 hi/lo ----
        float S[8][4];
        #pragma unroll
        for (int n = 0; n < 8; n++)
            #pragma unroll
            for (int j = 0; j < 4; j++) S[n][j] = 0.0f;

        #pragma unroll
        for (int k = 0; k < 8; k++) {
            uint32_t ah[4], al[4];
            uint32_t ao = aoff_base + ((uint32_t)(((k << 1) + achunk) ^ aswz) << 4);
            ldsm4(ah, sb + OFF_QHI + ao);
            ldsm4(al, sb + OFF_QLO + ao);
            #pragma unroll
            for (int n = 0; n < 8; n++) {
                uint32_t bh[2], bl[2];
                uint32_t bo = ((uint32_t)n << 11) + ((uint32_t)(lane & 7) << 8)
                            + ((uint32_t)((((k << 1) + ((lane >> 3) & 1))) ^ (lane & 7)) << 4);
                ldsm2(bh, sb + OFF_KHI + bo);
                ldsm2(bl, sb + OFF_KLO + bo);
                mma16816(S[n], ah, bh);
                mma16816(S[n], ah, bl);
                mma16816(S[n], al, bh);
            }
        }

        // ---- masking + online softmax (registers + quad shuffles) ----
        float mx0 = m0, mx1 = m1;
        #pragma unroll
        for (int n = 0; n < 8; n++) {
            int cbase = n * 8 + qr * 2;         // local key col
            int cg = k0 + cbase;                // global key idx
            int sk0 = sSegK[cbase], sk1 = sSegK[cbase + 1];
            bool a00 = (sk0 == sq0) && (cg     <= row0);
            bool a01 = (sk1 == sq0) && (cg + 1 <= row0);
            bool a10 = (sk0 == sq1) && (cg     <= row0 + 8);
            bool a11 = (sk1 == sq1) && (cg + 1 <= row0 + 8);
            S[n][0] = a00 ? S[n][0] : NEG;
            S[n][1] = a01 ? S[n][1] : NEG;
            S[n][2] = a10 ? S[n][2] : NEG;
            S[n][3] = a11 ? S[n][3] : NEG;
            mx0 = fmaxf(mx0, fmaxf(S[n][0], S[n][1]));
            mx1 = fmaxf(mx1, fmaxf(S[n][2], S[n][3]));
        }
        mx0 = fmaxf(mx0, __shfl_xor_sync(0xffffffffu, mx0, 1));
        mx0 = fmaxf(mx0, __shfl_xor_sync(0xffffffffu, mx0, 2));
        mx1 = fmaxf(mx1, __shfl_xor_sync(0xffffffffu, mx1, 1));
        mx1 = fmaxf(mx1, __shfl_xor_sync(0xffffffffu, mx1, 2));

        float sc0 = __expf(m0 - mx0);
        float sc1 = __expf(m1 - mx1);
        m0 = mx0; m1 = mx1;

        float s0 = 0.0f, s1 = 0.0f;
        #pragma unroll
        for (int n = 0; n < 8; n++) {
            float e0 = __expf(S[n][0] - mx0);
            float e1 = __expf(S[n][1] - mx0);
            float e2 = __expf(S[n][2] - mx1);
            float e3 = __expf(S[n][3] - mx1);
            S[n][0] = e0; S[n][1] = e1; S[n][2] = e2; S[n][3] = e3;
            s0 += e0 + e1; s1 += e2 + e3;
        }
        s0 += __shfl_xor_sync(0xffffffffu, s0, 1);
        s0 += __shfl_xor_sync(0xffffffffu, s0, 2);
        s1 += __shfl_xor_sync(0xffffffffu, s1, 1);
        s1 += __shfl_xor_sync(0xffffffffu, s1, 2);
        l0 = l0 * sc0 + s0;
        l1 = l1 * sc1 + s1;

        // rescale O accumulators
        #pragma unroll
        for (int nd = 0; nd < 16; nd++) {
            Oa[nd][0] *= sc0; Oa[nd][1] *= sc0;
            Oa[nd][2] *= sc1; Oa[nd][3] *= sc1;
        }

        // ---- pack P into PV A-fragments (hi/lo), no smem round-trip ----
        uint32_t PH[4][4], PL[4][4];
        #pragma unroll
        for (int kc = 0; kc < 4; kc++) {
            split2(S[2*kc][0],   S[2*kc][1],   PH[kc][0], PL[kc][0]);
            split2(S[2*kc][2],   S[2*kc][3],   PH[kc][1], PL[kc][1]);
            split2(S[2*kc+1][0], S[2*kc+1][1], PH[kc][2], PL[kc][2]);
            split2(S[2*kc+1][2], S[2*kc+1][3], PH[kc][3], PL[kc][3]);
        }

        // ---- PV: O += P(16x64) @ V(64x128), 3-pass ----
        #pragma unroll
        for (int kc = 0; kc < 4; kc++) {
            #pragma unroll
            for (int nd = 0; nd < 16; nd++) {
                uint32_t bh[2], bl[2];
                uint32_t vo = ((uint32_t)kc << 12) + ((uint32_t)(lane & 15) << 8)
                            + ((uint32_t)(nd ^ (lane & 7)) << 4);
                ldsm2t(bh, sb + OFF_VHI + vo);
                ldsm2t(bl, sb + OFF_VLO + vo);
                mma16816(Oa[nd], PH[kc], bh);
                mma16816(Oa[nd], PH[kc], bl);
                mma16816(Oa[nd], PL[kc], bh);
            }
        }
    }

    // ---- epilogue ----
    const float inv0 = 1.0f / l0;
    const float inv1 = 1.0f / l1;
    float* o0 = Out + ((size_t)((b * Tseq + row0) * NQH + h)) * Dh;
    float* o1 = Out + ((size_t)((b * Tseq + row0 + 8) * NQH + h)) * Dh;
    #pragma unroll
    for (int nd = 0; nd < 16; nd++) {
        int d = nd * 8 + qr * 2;
        float2 w0 = make_float2(Oa[nd][0] * inv0, Oa[nd][1] * inv0);
        float2 w1 = make_float2(Oa[nd][2] * inv1, Oa[nd][3] * inv1);
        *(float2*)(o0 + d) = w0;
        *(float2*)(o1 + d) = w1;
    }
}

extern "C" void kernel_launch(void* const* d_in, const int* in_sizes, int n_in,
                              void* d_out, int out_size)
{
    const float* Q   = (const float*)d_in[0];
    const float* K   = (const float*)d_in[1];
    const float* V   = (const float*)d_in[2];
    const int*   seg = (const int*)d_in[3];
    float*       O   = (float*)d_out;

    cudaFuncSetAttribute(attn_hmma_kernel,
                         cudaFuncAttributeMaxDynamicSharedMemorySize, SMEM_TOTAL);

    dim3 grid(Tseq / BM, NQH, Bsz);
    attn_hmma_kernel<<<grid, NTHREADS, SMEM_TOTAL>>>(Q, K, V, seg, O);
}

// round 4
// speedup vs baseline: 3.8812x; 1.2974x over previous
#include <cuda_runtime.h>
#include <cuda_fp16.h>
#include <cstdint>

// ---------------- problem constants ----------------
#define Bsz   2
#define Tseq  1024
#define NQH   32
#define NKV   8
#define Dh    128
#define BM    64         // query rows per CTA
#define BN    64         // key rows per tile
#define NTHREADS 128
#define MASKV (-3.0e38f)

// ---------------- smem layout (bytes) ----------------
// fp16 tiles, 256B rows (128 halves), XOR-swizzled 16B chunks
#define OFF_QHI 0
#define OFF_QLO 16384
#define OFF_KHI 32768
#define OFF_KLO 49152
#define OFF_VHI 65536
#define OFF_SEGK 81920
#define SMEM_TOTAL (81920 + 256 + 128)

__device__ __forceinline__ uint32_t smem_u32(const void* p) {
    uint32_t a;
    asm("{ .reg .u64 t; cvta.to.shared.u64 t, %1; cvt.u32.u64 %0, t; }"
        : "=r"(a) : "l"(p));
    return a;
}

// swizzled byte offset of 16B chunk (row, c) in a 256B-row tile
__device__ __forceinline__ uint32_t toff(int row, int c) {
    return ((uint32_t)row << 8) + (((uint32_t)(c ^ (row & 7))) << 4);
}

__device__ __forceinline__ void ldsm4(uint32_t* r, uint32_t a) {
    asm volatile("ldmatrix.sync.aligned.m8n8.x4.shared.b16 {%0,%1,%2,%3}, [%4];"
                 : "=r"(r[0]), "=r"(r[1]), "=r"(r[2]), "=r"(r[3]) : "r"(a));
}
__device__ __forceinline__ void ldsm4t(uint32_t* r, uint32_t a) {
    asm volatile("ldmatrix.sync.aligned.m8n8.x4.trans.shared.b16 {%0,%1,%2,%3}, [%4];"
                 : "=r"(r[0]), "=r"(r[1]), "=r"(r[2]), "=r"(r[3]) : "r"(a));
}
__device__ __forceinline__ void mma16816(float* d, const uint32_t* a, const uint32_t* b) {
    asm volatile("mma.sync.aligned.m16n8k16.row.col.f32.f16.f16.f32 "
                 "{%0,%1,%2,%3}, {%4,%5,%6,%7}, {%8,%9}, {%0,%1,%2,%3};"
                 : "+f"(d[0]), "+f"(d[1]), "+f"(d[2]), "+f"(d[3])
                 : "r"(a[0]), "r"(a[1]), "r"(a[2]), "r"(a[3]),
                   "r"(b[0]), "r"(b[1]));
}

// pack two floats -> half2 (lo, hi)
__device__ __forceinline__ uint32_t pack_h2(float lo, float hi) {
    uint32_t r;
    asm("cvt.rn.f16x2.f32 %0, %1, %2;" : "=r"(r) : "f"(hi), "f"(lo));
    return r;
}

// split (x,y) into fp16 hi pair + fp16 residual-lo pair
__device__ __forceinline__ void split2(float x, float y, uint32_t& h, uint32_t& l) {
    __half hx = __float2half_rn(x), hy = __float2half_rn(y);
    __half lx = __float2half_rn(x - __half2float(hx));
    __half ly = __float2half_rn(y - __half2float(hy));
    __half2 hh = __halves2half2(hx, hy);
    __half2 ll = __halves2half2(lx, ly);
    h = *(uint32_t*)&hh;
    l = *(uint32_t*)&ll;
}

// convert 8 floats -> hi/lo fp16 chunks, store as two st.shared.v4
__device__ __forceinline__ void cvt_sts8(uint32_t ahi, uint32_t alo, const float* v) {
    uint32_t h[4], l[4];
    #pragma unroll
    for (int i = 0; i < 4; i++)
        split2(v[2*i], v[2*i+1], h[i], l[i]);
    asm volatile("st.shared.v4.b32 [%0], {%1,%2,%3,%4};"
                 :: "r"(ahi), "r"(h[0]), "r"(h[1]), "r"(h[2]), "r"(h[3]) : "memory");
    asm volatile("st.shared.v4.b32 [%0], {%1,%2,%3,%4};"
                 :: "r"(alo), "r"(l[0]), "r"(l[1]), "r"(l[2]), "r"(l[3]) : "memory");
}

// convert 8 floats -> fp16 chunk (hi only), one st.shared.v4
__device__ __forceinline__ void cvt_sts4(uint32_t ahi, const float* v) {
    uint32_t h[4];
    #pragma unroll
    for (int i = 0; i < 4; i++)
        h[i] = pack_h2(v[2*i], v[2*i+1]);
    asm volatile("st.shared.v4.b32 [%0], {%1,%2,%3,%4};"
                 :: "r"(ahi), "r"(h[0]), "r"(h[1]), "r"(h[2]), "r"(h[3]) : "memory");
}

__global__ __launch_bounds__(NTHREADS, 2)
void attn_hmma_kernel(const float* __restrict__ Q,
                      const float* __restrict__ K,
                      const float* __restrict__ V,
                      const int*   __restrict__ seg,
                      float*       __restrict__ Out)
{
    extern __shared__ char smem[];
    const uint32_t sb = smem_u32(smem);
    const int tid  = threadIdx.x;
    const int wid  = tid >> 5;           // 0..3
    const int lane = tid & 31;
    const int quad = lane >> 2;
    const int qr   = lane & 3;

    const int qtile = blockIdx.x;        // 0..15
    const int h     = blockIdx.y;
    const int b     = blockIdx.z;
    const int kh    = h >> 2;
    const int q0    = qtile * BM;

    int* sSegK = (int*)(smem + OFF_SEGK);

    // ---- prologue: Q -> fp16 hi/lo smem (swizzled) ----
    #pragma unroll
    for (int it = 0; it < 8; it++) {
        int idx = tid + it * NTHREADS;
        int r = idx >> 4, c = idx & 15;
        const float* g = Q + ((size_t)((b * Tseq + q0 + r) * NQH + h)) * Dh + c * 8;
        float4 v0 = *(const float4*)g;
        float4 v1 = *(const float4*)(g + 4);
        float arr[8] = { v0.x, v0.y, v0.z, v0.w, v1.x, v1.y, v1.z, v1.w };
        uint32_t o = toff(r, c);
        cvt_sts8(sb + OFF_QHI + o, sb + OFF_QLO + o, arr);
    }

    // per-row segment ids for this thread's two fragment rows
    const int rowl0 = 16 * wid + quad;
    const int row0  = q0 + rowl0;
    const int sq0 = seg[b * Tseq + row0];
    const int sq1 = seg[b * Tseq + row0 + 8];
    const int sqmin = seg[b * Tseq + q0];
    const int sqmax = seg[b * Tseq + q0 + BM - 1];

    // A-operand ldmatrix addressing (Q tiles)
    const int rA    = 16 * wid + (lane & 15);
    const uint32_t aoff_base = (uint32_t)rA << 8;
    const int aswz   = rA & 7;
    const int achunk = lane >> 4;

    // B-operand (K) x4 addressing: row = np*16 + (lane>>4)*8 + (lane&7)
    const int brow_l = ((lane >> 4) << 3) + (lane & 7);
    const int bsel   = (lane >> 3) & 1;        // k-chunk parity
    const int bswz   = lane & 7;

    // V^T x4 trans addressing: row = kc*16 + (lane&15), chunk = nd + (lane>>4)
    const int vrow_l = lane & 15;
    const int vsel   = lane >> 4;

    float m0 = MASKV, m1 = MASKV, l0 = 0.0f, l1 = 0.0f;
    float Oa[16][4];
    #pragma unroll
    for (int i = 0; i < 16; i++)
        #pragma unroll
        for (int j = 0; j < 4; j++) Oa[i][j] = 0.0f;

    const float NEG = -__int_as_float(0x7f800000);   // -inf
    const int ktmax = qtile;

    for (int kt = 0; kt <= ktmax; kt++) {
        const int k0 = kt * BN;
        const int skmin = seg[b * Tseq + k0];
        const int skmax = seg[b * Tseq + k0 + BN - 1];
        if (skmax < sqmin || skmin > sqmax) continue;   // uniform skip

        __syncthreads();   // prior smem reads complete (and Q stores, first iter)

        // ---- K (hi/lo) and V (hi) tiles -> fp16 smem ----
        #pragma unroll
        for (int it = 0; it < 8; it++) {
            int idx = tid + it * NTHREADS;
            int r = idx >> 4, c = idx & 15;
            uint32_t o = toff(r, c);
            {
                const float* g = K + ((size_t)((b * Tseq + k0 + r) * NKV + kh)) * Dh + c * 8;
                float4 v0 = *(const float4*)g;
                float4 v1 = *(const float4*)(g + 4);
                float arr[8] = { v0.x, v0.y, v0.z, v0.w, v1.x, v1.y, v1.z, v1.w };
                cvt_sts8(sb + OFF_KHI + o, sb + OFF_KLO + o, arr);
            }
            {
                const float* g = V + ((size_t)((b * Tseq + k0 + r) * NKV + kh)) * Dh + c * 8;
                float4 v0 = *(const float4*)g;
                float4 v1 = *(const float4*)(g + 4);
                float arr[8] = { v0.x, v0.y, v0.z, v0.w, v1.x, v1.y, v1.z, v1.w };
                cvt_sts4(sb + OFF_VHI + o, arr);
            }
        }
        if (tid < BN) sSegK[tid] = seg[b * Tseq + k0 + tid];
        __syncthreads();

        // ---- QK: S(16x64 per warp) = qh*kh + qh*kl + ql*kh ----
        float S[8][4];
        #pragma unroll
        for (int n = 0; n < 8; n++)
            #pragma unroll
            for (int j = 0; j < 4; j++) S[n][j] = 0.0f;

        #pragma unroll
        for (int k = 0; k < 8; k++) {
            uint32_t ah[4], al[4];
            uint32_t ao = aoff_base + ((uint32_t)(((k << 1) + achunk) ^ aswz) << 4);
            ldsm4(ah, sb + OFF_QHI + ao);
            ldsm4(al, sb + OFF_QLO + ao);
            #pragma unroll
            for (int np = 0; np < 4; np++) {
                uint32_t bh[4], bl[4];
                uint32_t bo = ((uint32_t)(np * 16 + brow_l) << 8)
                            + ((uint32_t)(((k << 1) + bsel) ^ bswz) << 4);
                ldsm4(bh, sb + OFF_KHI + bo);
                ldsm4(bl, sb + OFF_KLO + bo);
                mma16816(S[2*np],   ah, bh);
                mma16816(S[2*np+1], ah, bh + 2);
                mma16816(S[2*np],   ah, bl);
                mma16816(S[2*np+1], ah, bl + 2);
                mma16816(S[2*np],   al, bh);
                mma16816(S[2*np+1], al, bh + 2);
            }
        }

        // ---- masking + online softmax (registers + quad shuffles) ----
        float mx0 = m0, mx1 = m1;
        #pragma unroll
        for (int n = 0; n < 8; n++) {
            int cbase = n * 8 + qr * 2;
            int cg = k0 + cbase;
            int sk0 = sSegK[cbase], sk1 = sSegK[cbase + 1];
            bool a00 = (sk0 == sq0) && (cg     <= row0);
            bool a01 = (sk1 == sq0) && (cg + 1 <= row0);
            bool a10 = (sk0 == sq1) && (cg     <= row0 + 8);
            bool a11 = (sk1 == sq1) && (cg + 1 <= row0 + 8);
            S[n][0] = a00 ? S[n][0] : NEG;
            S[n][1] = a01 ? S[n][1] : NEG;
            S[n][2] = a10 ? S[n][2] : NEG;
            S[n][3] = a11 ? S[n][3] : NEG;
            mx0 = fmaxf(mx0, fmaxf(S[n][0], S[n][1]));
            mx1 = fmaxf(mx1, fmaxf(S[n][2], S[n][3]));
        }
        mx0 = fmaxf(mx0, __shfl_xor_sync(0xffffffffu, mx0, 1));
        mx0 = fmaxf(mx0, __shfl_xor_sync(0xffffffffu, mx0, 2));
        mx1 = fmaxf(mx1, __shfl_xor_sync(0xffffffffu, mx1, 1));
        mx1 = fmaxf(mx1, __shfl_xor_sync(0xffffffffu, mx1, 2));

        float sc0 = __expf(m0 - mx0);
        float sc1 = __expf(m1 - mx1);
        m0 = mx0; m1 = mx1;

        float s0 = 0.0f, s1 = 0.0f;
        #pragma unroll
        for (int n = 0; n < 8; n++) {
            float e0 = __expf(S[n][0] - mx0);
            float e1 = __expf(S[n][1] - mx0);
            float e2 = __expf(S[n][2] - mx1);
            float e3 = __expf(S[n][3] - mx1);
            S[n][0] = e0; S[n][1] = e1; S[n][2] = e2; S[n][3] = e3;
            s0 += e0 + e1; s1 += e2 + e3;
        }
        s0 += __shfl_xor_sync(0xffffffffu, s0, 1);
        s0 += __shfl_xor_sync(0xffffffffu, s0, 2);
        s1 += __shfl_xor_sync(0xffffffffu, s1, 1);
        s1 += __shfl_xor_sync(0xffffffffu, s1, 2);
        l0 = l0 * sc0 + s0;
        l1 = l1 * sc1 + s1;

        // rescale O accumulators
        #pragma unroll
        for (int nd = 0; nd < 16; nd++) {
            Oa[nd][0] *= sc0; Oa[nd][1] *= sc0;
            Oa[nd][2] *= sc1; Oa[nd][3] *= sc1;
        }

        // ---- pack P (fp16) into PV A-fragments, no smem round-trip ----
        uint32_t PH[4][4];
        #pragma unroll
        for (int kc = 0; kc < 4; kc++) {
            PH[kc][0] = pack_h2(S[2*kc][0],   S[2*kc][1]);
            PH[kc][1] = pack_h2(S[2*kc][2],   S[2*kc][3]);
            PH[kc][2] = pack_h2(S[2*kc+1][0], S[2*kc+1][1]);
            PH[kc][3] = pack_h2(S[2*kc+1][2], S[2*kc+1][3]);
        }

        // ---- PV: O += P(16x64) @ V(64x128), single pass ----
        #pragma unroll
        for (int kc = 0; kc < 4; kc++) {
            #pragma unroll
            for (int ndp = 0; ndp < 8; ndp++) {
                uint32_t vh[4];
                uint32_t vo = ((uint32_t)(kc * 16 + vrow_l) << 8)
                            + ((uint32_t)((2 * ndp + vsel) ^ bswz) << 4);
                ldsm4t(vh, sb + OFF_VHI + vo);
                mma16816(Oa[2*ndp],   PH[kc], vh);
                mma16816(Oa[2*ndp+1], PH[kc], vh + 2);
            }
        }
    }

    // ---- epilogue ----
    const float inv0 = 1.0f / l0;
    const float inv1 = 1.0f / l1;
    float* o0 = Out + ((size_t)((b * Tseq + row0) * NQH + h)) * Dh;
    float* o1 = Out + ((size_t)((b * Tseq + row0 + 8) * NQH + h)) * Dh;
    #pragma unroll
    for (int nd = 0; nd < 16; nd++) {
        int d = nd * 8 + qr * 2;
        float2 w0 = make_float2(Oa[nd][0] * inv0, Oa[nd][1] * inv0);
        float2 w1 = make_float2(Oa[nd][2] * inv1, Oa[nd][3] * inv1);
        *(float2*)(o0 + d) = w0;
        *(float2*)(o1 + d) = w1;
    }
}

extern "C" void kernel_launch(void* const* d_in, const int* in_sizes, int n_in,
                              void* d_out, int out_size)
{
    const float* Q   = (const float*)d_in[0];
    const float* K   = (const float*)d_in[1];
    const float* V   = (const float*)d_in[2];
    const int*   seg = (const int*)d_in[3];
    float*       O   = (float*)d_out;

    cudaFuncSetAttribute(attn_hmma_kernel,
                         cudaFuncAttributeMaxDynamicSharedMemorySize, SMEM_TOTAL);

    dim3 grid(Tseq / BM, NQH, Bsz);
    attn_hmma_kernel<<<grid, NTHREADS, SMEM_TOTAL>>>(Q, K, V, seg, O);
}

// round 6
// speedup vs baseline: 3.9581x; 1.0198x over previous
#include <cuda_runtime.h>
#include <cuda_fp16.h>
#include <cstdint>

// ---------------- problem constants ----------------
#define Bsz   2
#define Tseq  1024
#define NQH   32
#define NKV   8
#define Dh    128
#define BM    64         // query rows per CTA
#define BN    64         // key rows per tile
#define NTHREADS 128
#define LOG2E 1.4426950408889634f
// running-max init: must satisfy |MINIT*LOG2E| < FLT_MAX (NaN fix for R5)
#define MINIT (-1.0e30f)

// ---------------- smem layout (bytes) ----------------
// QLO:   [0, 16384)                       Q residual-lo, persistent
// BUF b: [16384 + b*49152, +49152)        KHI(16K) | KLO(16K) | VHI(16K)
// SEG b: [114688 + b*256, +256)
#define OFF_QLO  0
#define OFF_BUF  16384
#define BUFSZ    49152
#define KLO_OFF  16384
#define VHI_OFF  32768
#define OFF_SEG  114688
#define SMEM_TOTAL (OFF_SEG + 512)   // 115,200 B -> 2 CTAs/SM (227KB total)

__device__ __forceinline__ uint32_t smem_u32(const void* p) {
    uint32_t a;
    asm("{ .reg .u64 t; cvta.to.shared.u64 t, %1; cvt.u32.u64 %0, t; }"
        : "=r"(a) : "l"(p));
    return a;
}

// swizzled byte offset of 16B chunk (row, c) in a 256B-row tile
__device__ __forceinline__ uint32_t toff(int row, int c) {
    return ((uint32_t)row << 8) + (((uint32_t)(c ^ (row & 7))) << 4);
}

__device__ __forceinline__ void ldsm4(uint32_t* r, uint32_t a) {
    asm volatile("ldmatrix.sync.aligned.m8n8.x4.shared.b16 {%0,%1,%2,%3}, [%4];"
                 : "=r"(r[0]), "=r"(r[1]), "=r"(r[2]), "=r"(r[3]) : "r"(a));
}
__device__ __forceinline__ void ldsm4t(uint32_t* r, uint32_t a) {
    asm volatile("ldmatrix.sync.aligned.m8n8.x4.trans.shared.b16 {%0,%1,%2,%3}, [%4];"
                 : "=r"(r[0]), "=r"(r[1]), "=r"(r[2]), "=r"(r[3]) : "r"(a));
}
__device__ __forceinline__ void mma16816(float* d, const uint32_t* a, const uint32_t* b) {
    asm volatile("mma.sync.aligned.m16n8k16.row.col.f32.f16.f16.f32 "
                 "{%0,%1,%2,%3}, {%4,%5,%6,%7}, {%8,%9}, {%0,%1,%2,%3};"
                 : "+f"(d[0]), "+f"(d[1]), "+f"(d[2]), "+f"(d[3])
                 : "r"(a[0]), "r"(a[1]), "r"(a[2]), "r"(a[3]),
                   "r"(b[0]), "r"(b[1]));
}

// pack two floats -> half2 (lo in low half)
__device__ __forceinline__ uint32_t pack_h2(float lo, float hi) {
    uint32_t r;
    asm("cvt.rn.f16x2.f32 %0, %1, %2;" : "=r"(r) : "f"(hi), "f"(lo));
    return r;
}
__device__ __forceinline__ uint32_t ex2_h2(uint32_t x) {
    uint32_t r;
    asm("ex2.approx.f16x2 %0, %1;" : "=r"(r) : "r"(x));
    return r;
}

// split (x,y) into fp16 hi pair + fp16 residual-lo pair
__device__ __forceinline__ void split2(float x, float y, uint32_t& h, uint32_t& l) {
    __half hx = __float2half_rn(x), hy = __float2half_rn(y);
    __half lx = __float2half_rn(x - __half2float(hx));
    __half ly = __float2half_rn(y - __half2float(hy));
    __half2 hh = __halves2half2(hx, hy);
    __half2 ll = __halves2half2(lx, ly);
    h = *(uint32_t*)&hh;
    l = *(uint32_t*)&ll;
}

// 8 floats -> hi/lo fp16 chunks (two st.shared.v4)
__device__ __forceinline__ void cvt_sts8(uint32_t ahi, uint32_t alo, const float* v) {
    uint32_t h[4], l[4];
    #pragma unroll
    for (int i = 0; i < 4; i++)
        split2(v[2*i], v[2*i+1], h[i], l[i]);
    asm volatile("st.shared.v4.b32 [%0], {%1,%2,%3,%4};"
                 :: "r"(ahi), "r"(h[0]), "r"(h[1]), "r"(h[2]), "r"(h[3]) : "memory");
    asm volatile("st.shared.v4.b32 [%0], {%1,%2,%3,%4};"
                 :: "r"(alo), "r"(l[0]), "r"(l[1]), "r"(l[2]), "r"(l[3]) : "memory");
}
// 8 floats -> fp16 chunk (hi only)
__device__ __forceinline__ void cvt_sts4(uint32_t ahi, const float* v) {
    uint32_t h[4];
    #pragma unroll
    for (int i = 0; i < 4; i++)
        h[i] = pack_h2(v[2*i], v[2*i+1]);
    asm volatile("st.shared.v4.b32 [%0], {%1,%2,%3,%4};"
                 :: "r"(ahi), "r"(h[0]), "r"(h[1]), "r"(h[2]), "r"(h[3]) : "memory");
}

// load K tile (fp32 gmem) -> KHI/KLO smem (+ seg ids)
__device__ __forceinline__ void load_K(const float* __restrict__ Kg,
                                       const int* __restrict__ seg,
                                       uint32_t kbase, int* sSegDst,
                                       int b, int k0, int kh, int tid)
{
    #pragma unroll
    for (int it = 0; it < 8; it++) {
        int idx = tid + it * NTHREADS;
        int r = idx >> 4, c = idx & 15;
        const float* g = Kg + ((size_t)((b * Tseq + k0 + r) * NKV + kh)) * Dh + c * 8;
        float4 v0 = *(const float4*)g;
        float4 v1 = *(const float4*)(g + 4);
        float arr[8] = { v0.x, v0.y, v0.z, v0.w, v1.x, v1.y, v1.z, v1.w };
        uint32_t o = toff(r, c);
        cvt_sts8(kbase + o, kbase + KLO_OFF + o, arr);
    }
    if (tid < BN) sSegDst[tid] = seg[b * Tseq + k0 + tid];
}

// load V tile (fp32 gmem) -> VHI smem
__device__ __forceinline__ void load_V(const float* __restrict__ Vg,
                                       uint32_t vbase,
                                       int b, int k0, int kh, int tid)
{
    #pragma unroll
    for (int it = 0; it < 8; it++) {
        int idx = tid + it * NTHREADS;
        int r = idx >> 4, c = idx & 15;
        const float* g = Vg + ((size_t)((b * Tseq + k0 + r) * NKV + kh)) * Dh + c * 8;
        float4 v0 = *(const float4*)g;
        float4 v1 = *(const float4*)(g + 4);
        float arr[8] = { v0.x, v0.y, v0.z, v0.w, v1.x, v1.y, v1.z, v1.w };
        cvt_sts4(vbase + toff(r, c), arr);
    }
}

__global__ __launch_bounds__(NTHREADS, 2)
void attn_hmma_kernel(const float* __restrict__ Q,
                      const float* __restrict__ K,
                      const float* __restrict__ V,
                      const int*   __restrict__ seg,
                      float*       __restrict__ Out)
{
    extern __shared__ char smem[];
    const uint32_t sb = smem_u32(smem);
    const int tid  = threadIdx.x;
    const int wid  = tid >> 5;
    const int lane = tid & 31;
    const int quad = lane >> 2;
    const int qr   = lane & 3;

    const int qtile = blockIdx.x;
    const int h     = blockIdx.y;
    const int b     = blockIdx.z;
    const int kh    = h >> 2;
    const int q0    = qtile * BM;

    // ---- prologue: Q -> fp16 hi (staging in BUF1.KHI) + lo (QLO) ----
    const uint32_t qstage = sb + OFF_BUF + BUFSZ;   // BUF1 KHI region
    #pragma unroll
    for (int it = 0; it < 8; it++) {
        int idx = tid + it * NTHREADS;
        int r = idx >> 4, c = idx & 15;
        const float* g = Q + ((size_t)((b * Tseq + q0 + r) * NQH + h)) * Dh + c * 8;
        float4 v0 = *(const float4*)g;
        float4 v1 = *(const float4*)(g + 4);
        float arr[8] = { v0.x, v0.y, v0.z, v0.w, v1.x, v1.y, v1.z, v1.w };
        uint32_t o = toff(r, c);
        cvt_sts8(qstage + o, sb + OFF_QLO + o, arr);
    }

    const int rowl0 = 16 * wid + quad;
    const int row0  = q0 + rowl0;
    const int sq0 = seg[b * Tseq + row0];
    const int sq1 = seg[b * Tseq + row0 + 8];
    const int sqmin = seg[b * Tseq + q0];
    const int sqmax = seg[b * Tseq + q0 + BM - 1];

    // ldmatrix addressing
    const int rA    = 16 * wid + (lane & 15);
    const uint32_t aoff_base = (uint32_t)rA << 8;
    const int aswz   = rA & 7;
    const int achunk = lane >> 4;
    const int brow_l = ((lane >> 4) << 3) + (lane & 7);
    const int bsel   = (lane >> 3) & 1;
    const int bswz   = lane & 7;
    const int vrow_l = lane & 15;
    const int vsel   = lane >> 4;

    const int ktmax = qtile;
    auto inactive = [&](int t) -> bool {
        int s0 = seg[b * Tseq + t * BN];
        int s1 = seg[b * Tseq + t * BN + BN - 1];
        return (s1 < sqmin) | (s0 > sqmax);
    };

    int kt = 0;
    while (kt < ktmax && inactive(kt)) kt++;   // diagonal tile always active

    __syncthreads();   // Q staging visible

    // persistent Q-hi fragments
    uint32_t Qh[8][4];
    #pragma unroll
    for (int k = 0; k < 8; k++) {
        uint32_t ao = aoff_base + ((uint32_t)(((k << 1) + achunk) ^ aswz) << 4);
        ldsm4(Qh[k], qstage + ao);
    }

    // preload first tile into BUF0
    load_K(K, seg, sb + OFF_BUF, (int*)(smem + OFF_SEG), b, kt * BN, kh, tid);
    load_V(V, sb + OFF_BUF + VHI_OFF, b, kt * BN, kh, tid);

    float m0 = MINIT, m1 = MINIT, l0 = 0.0f, l1 = 0.0f;
    float Oa[16][4];
    #pragma unroll
    for (int i = 0; i < 16; i++)
        #pragma unroll
        for (int j = 0; j < 4; j++) Oa[i][j] = 0.0f;

    const float NEG = -__int_as_float(0x7f800000);   // -inf
    const uint32_t ONES2[2] = { 0x3C003C00u, 0x3C003C00u };
    int cur = 0;

    while (kt <= ktmax) {
        __syncthreads();   // buf[cur] ready; buf[cur^1] free to overwrite
        const int k0 = kt * BN;

        int ktn = kt + 1;
        while (ktn <= ktmax && inactive(ktn)) ktn++;
        const bool hasn = (ktn <= ktmax);

        const uint32_t cbase = sb + OFF_BUF + cur * BUFSZ;
        const uint32_t nbase = sb + OFF_BUF + (cur ^ 1) * BUFSZ;
        int* segCur = (int*)(smem + OFF_SEG + cur * 256);
        int* segNxt = (int*)(smem + OFF_SEG + (cur ^ 1) * 256);

        // ---- prefetch next K (overlaps QK below) ----
        if (hasn) load_K(K, seg, nbase, segNxt, b, ktn * BN, kh, tid);

        // ---- QK: S = qh*kh + qh*kl + ql*kh ----
        float S[8][4];
        #pragma unroll
        for (int n = 0; n < 8; n++)
            #pragma unroll
            for (int j = 0; j < 4; j++) S[n][j] = 0.0f;

        #pragma unroll
        for (int k = 0; k < 8; k++) {
            uint32_t al[4];
            uint32_t ao = aoff_base + ((uint32_t)(((k << 1) + achunk) ^ aswz) << 4);
            ldsm4(al, sb + OFF_QLO + ao);
            #pragma unroll
            for (int np = 0; np < 4; np++) {
                uint32_t bh[4], bl[4];
                uint32_t bo = ((uint32_t)(np * 16 + brow_l) << 8)
                            + ((uint32_t)(((k << 1) + bsel) ^ bswz) << 4);
                ldsm4(bh, cbase + bo);
                ldsm4(bl, cbase + KLO_OFF + bo);
                mma16816(S[2*np],   Qh[k], bh);
                mma16816(S[2*np+1], Qh[k], bh + 2);
                mma16816(S[2*np],   Qh[k], bl);
                mma16816(S[2*np+1], Qh[k], bl + 2);
                mma16816(S[2*np],   al, bh);
                mma16816(S[2*np+1], al, bh + 2);
            }
        }

        // ---- prefetch next V ----
        if (hasn) load_V(V, nbase + VHI_OFF, b, ktn * BN, kh, tid);

        // ---- masking + row max ----
        float mx0 = m0, mx1 = m1;
        #pragma unroll
        for (int n = 0; n < 8; n++) {
            int cbase_c = n * 8 + qr * 2;
            int cg = k0 + cbase_c;
            int sk0 = segCur[cbase_c], sk1 = segCur[cbase_c + 1];
            bool a00 = (sk0 == sq0) && (cg     <= row0);
            bool a01 = (sk1 == sq0) && (cg + 1 <= row0);
            bool a10 = (sk0 == sq1) && (cg     <= row0 + 8);
            bool a11 = (sk1 == sq1) && (cg + 1 <= row0 + 8);
            S[n][0] = a00 ? S[n][0] : NEG;
            S[n][1] = a01 ? S[n][1] : NEG;
            S[n][2] = a10 ? S[n][2] : NEG;
            S[n][3] = a11 ? S[n][3] : NEG;
            mx0 = fmaxf(mx0, fmaxf(S[n][0], S[n][1]));
            mx1 = fmaxf(mx1, fmaxf(S[n][2], S[n][3]));
        }
        mx0 = fmaxf(mx0, __shfl_xor_sync(0xffffffffu, mx0, 1));
        mx0 = fmaxf(mx0, __shfl_xor_sync(0xffffffffu, mx0, 2));
        mx1 = fmaxf(mx1, __shfl_xor_sync(0xffffffffu, mx1, 1));
        mx1 = fmaxf(mx1, __shfl_xor_sync(0xffffffffu, mx1, 2));

        float sc0 = __expf(m0 - mx0);
        float sc1 = __expf(m1 - mx1);
        m0 = mx0; m1 = mx1;

        // ---- exp2 in fp16x2: P fragments directly ----
        // mx >= MINIT=-1e30 -> |c| <= 1.44e30 finite (no inf-inf NaN)
        const float c0 = -mx0 * LOG2E;
        const float c1 = -mx1 * LOG2E;
        uint32_t PH[4][4];
        #pragma unroll
        for (int n = 0; n < 8; n++) {
            float t0 = fmaf(S[n][0], LOG2E, c0);
            float t1 = fmaf(S[n][1], LOG2E, c0);
            float t2 = fmaf(S[n][2], LOG2E, c1);
            float t3 = fmaf(S[n][3], LOG2E, c1);
            uint32_t p01 = ex2_h2(pack_h2(t0, t1));
            uint32_t p23 = ex2_h2(pack_h2(t2, t3));
            PH[n >> 1][(n & 1) << 1]       = p01;
            PH[n >> 1][((n & 1) << 1) | 1] = p23;
        }

        // ---- row sums via ones-MMA ----
        float Lacc[4] = { 0.0f, 0.0f, 0.0f, 0.0f };
        #pragma unroll
        for (int kc = 0; kc < 4; kc++)
            mma16816(Lacc, PH[kc], ONES2);
        l0 = l0 * sc0 + Lacc[0];
        l1 = l1 * sc1 + Lacc[2];

        // ---- rescale O ----
        #pragma unroll
        for (int nd = 0; nd < 16; nd++) {
            Oa[nd][0] *= sc0; Oa[nd][1] *= sc0;
            Oa[nd][2] *= sc1; Oa[nd][3] *= sc1;
        }

        // ---- PV on current V ----
        #pragma unroll
        for (int kc = 0; kc < 4; kc++) {
            #pragma unroll
            for (int ndp = 0; ndp < 8; ndp++) {
                uint32_t vh[4];
                uint32_t vo = ((uint32_t)(kc * 16 + vrow_l) << 8)
                            + ((uint32_t)((2 * ndp + vsel) ^ bswz) << 4);
                ldsm4t(vh, cbase + VHI_OFF + vo);
                mma16816(Oa[2*ndp],   PH[kc], vh);
                mma16816(Oa[2*ndp+1], PH[kc], vh + 2);
            }
        }

        kt = ktn;
        cur ^= 1;
    }

    // ---- epilogue ----
    const float inv0 = 1.0f / l0;
    const float inv1 = 1.0f / l1;
    float* o0 = Out + ((size_t)((b * Tseq + row0) * NQH + h)) * Dh;
    float* o1 = Out + ((size_t)((b * Tseq + row0 + 8) * NQH + h)) * Dh;
    #pragma unroll
    for (int nd = 0; nd < 16; nd++) {
        int d = nd * 8 + qr * 2;
        float2 w0 = make_float2(Oa[nd][0] * inv0, Oa[nd][1] * inv0);
        float2 w1 = make_float2(Oa[nd][2] * inv1, Oa[nd][3] * inv1);
        *(float2*)(o0 + d) = w0;
        *(float2*)(o1 + d) = w1;
    }
}

extern "C" void kernel_launch(void* const* d_in, const int* in_sizes, int n_in,
                              void* d_out, int out_size)
{
    const float* Q   = (const float*)d_in[0];
    const float* K   = (const float*)d_in[1];
    const float* V   = (const float*)d_in[2];
    const int*   seg = (const int*)d_in[3];
    float*       O   = (float*)d_out;

    cudaFuncSetAttribute(attn_hmma_kernel,
                         cudaFuncAttributeMaxDynamicSharedMemorySize, SMEM_TOTAL);

    dim3 grid(Tseq / BM, NQH, Bsz);
    attn_hmma_kernel<<<grid, NTHREADS, SMEM_TOTAL>>>(Q, K, V, seg, O);
}